// round 17
// baseline (speedup 1.0000x reference)
#include <cuda_runtime.h>
#include <math.h>
#include <stdint.h>

#define B   64
#define T   512
#define F   64
#define H   256
#define G   (3*H)   /* 768 */
#define D   64

#define CLU 8        /* CTAs per cluster */
#define KS  (H/CLU)  /* 32 rows / hidden units per CTA */
#define NB  4        /* batches per cluster */
#define TPB 256
#define RPAD 36      /* Rt row stride: 144B; 36%32==4 -> conflict-free LDS.128 */

typedef unsigned long long ull;

__device__ float g_xproj[B * T * G];

// ---------------------------------------------------------------------------
// PTX helpers (proven across R10/R14/R16 runs)
// ---------------------------------------------------------------------------
__device__ __forceinline__ uint32_t smem_u32(const void* p) {
    return (uint32_t)__cvta_generic_to_shared(p);
}
__device__ __forceinline__ uint32_t mapa_cluster(uint32_t addr, uint32_t rank) {
    uint32_t r;
    asm("mapa.shared::cluster.u32 %0, %1, %2;" : "=r"(r) : "r"(addr), "r"(rank));
    return r;
}
__device__ __forceinline__ void cluster_sync() {
    asm volatile("barrier.cluster.arrive.aligned;" ::: "memory");
    asm volatile("barrier.cluster.wait.aligned;"   ::: "memory");
}
__device__ __forceinline__ uint32_t ctarank() {
    uint32_t r;
    asm("mov.u32 %0, %%cluster_ctarank;" : "=r"(r));
    return r;
}
__device__ __forceinline__ void mbar_init(uint32_t addr, uint32_t cnt) {
    asm volatile("mbarrier.init.shared.b64 [%0], %1;" :: "r"(addr), "r"(cnt) : "memory");
}
__device__ __forceinline__ void mbar_expect_tx(uint32_t addr, uint32_t bytes) {
    asm volatile("mbarrier.arrive.expect_tx.shared.b64 _, [%0], %1;"
                 :: "r"(addr), "r"(bytes) : "memory");
}
__device__ __forceinline__ void mbar_wait(uint32_t addr, uint32_t parity) {
    asm volatile(
        "{\n\t"
        ".reg .pred P;\n"
        "WL_%=:\n\t"
        "mbarrier.try_wait.parity.acquire.cluster.shared::cta.b64 P, [%0], %1;\n\t"
        "@P bra WD_%=;\n\t"
        "bra WL_%=;\n"
        "WD_%=:\n\t"
        "}"
        :: "r"(addr), "r"(parity) : "memory");
}
__device__ __forceinline__ void st_async_f32(uint32_t addr, float v, uint32_t mbar) {
    asm volatile("st.async.shared::cluster.mbarrier::complete_tx::bytes.f32 [%0], %1, [%2];"
                 :: "r"(addr), "f"(v), "r"(mbar) : "memory");
}
__device__ __forceinline__ void lds_v2b64(ull& a, ull& b, uint32_t addr) {
    asm volatile("ld.shared.v2.b64 {%0, %1}, [%2];" : "=l"(a), "=l"(b) : "r"(addr));
}
__device__ __forceinline__ ull ffma2(ull a, ull b, ull c) {
    ull d;
    asm("fma.rn.f32x2 %0, %1, %2, %3;" : "=l"(d) : "l"(a), "l"(b), "l"(c));
    return d;
}
__device__ __forceinline__ ull pack2(float lo, float hi) {
    ull r;
    asm("mov.b64 %0, {%1, %2};" : "=l"(r) : "f"(lo), "f"(hi));
    return r;
}
__device__ __forceinline__ float red2(ull a) {
    float lo, hi;
    asm("mov.b64 {%0, %1}, %2;" : "=f"(lo), "=f"(hi) : "l"(a));
    return lo + hi;
}
__device__ __forceinline__ float sigmoid_f(float x) {
    return __fdividef(1.0f, 1.0f + __expf(-x));
}
__device__ __forceinline__ float tanh_f(float x) {
    const float e = __expf(2.0f * x);
    return 1.0f - __fdividef(2.0f, e + 1.0f);
}

// ---------------------------------------------------------------------------
// Kernel A: xproj = x @ kernel + bias  (EXACT proven 99.5us version)
// ---------------------------------------------------------------------------
#define XP_ROWS 16
#define XP_TPB  384
__global__ void __launch_bounds__(XP_TPB) xproj_kernel(
    const float* __restrict__ x, const float* __restrict__ w,
    const float* __restrict__ bias)
{
    __shared__ __align__(16) float xs[XP_ROWS * F];   // 4 KB
    const int col0 = threadIdx.x;          // 0..383
    const int col1 = col0 + XP_TPB;        // 384..767
    const int row0 = blockIdx.x * XP_ROWS;

    const float4* xin = (const float4*)(x + (size_t)row0 * F);
    for (int i = threadIdx.x; i < XP_ROWS * F / 4; i += XP_TPB)
        ((float4*)xs)[i] = xin[i];
    __syncthreads();

    ull accA[XP_ROWS], accB[XP_ROWS];
#pragma unroll
    for (int r = 0; r < XP_ROWS; r++) { accA[r] = 0ULL; accB[r] = 0ULL; }

    const uint32_t xs_a = smem_u32(xs);

#pragma unroll 4
    for (int k4 = 0; k4 < F / 4; k4++) {
        const int k = 4 * k4;
        const ull wa0 = pack2(w[(k + 0) * G + col0], w[(k + 1) * G + col0]);
        const ull wa1 = pack2(w[(k + 2) * G + col0], w[(k + 3) * G + col0]);
        const ull wb0 = pack2(w[(k + 0) * G + col1], w[(k + 1) * G + col1]);
        const ull wb1 = pack2(w[(k + 2) * G + col1], w[(k + 3) * G + col1]);
#pragma unroll
        for (int r = 0; r < XP_ROWS; r++) {
            ull x01, x23;
            lds_v2b64(x01, x23, xs_a + (uint32_t)(r * F + k) * 4u);
            accA[r] = ffma2(x01, wa0, accA[r]);
            accA[r] = ffma2(x23, wa1, accA[r]);
            accB[r] = ffma2(x01, wb0, accB[r]);
            accB[r] = ffma2(x23, wb1, accB[r]);
        }
    }

    const float bv0 = bias[col0];
    const float bv1 = bias[col1];
#pragma unroll
    for (int r = 0; r < XP_ROWS; r++) {
        g_xproj[(size_t)(row0 + r) * G + col0] = bv0 + red2(accA[r]);
        g_xproj[(size_t)(row0 + r) * G + col1] = bv1 + red2(accB[r]);
    }
}

// ---------------------------------------------------------------------------
// Kernel B: GRU scan — proven st.async+mbarrier protocol, new geometry:
// 8-CTA clusters, 4 batches/cluster, KS=32 rows/CTA.
// Thread j (0..255): gate columns j, H+j, 2H+j over local k in [0,32),
// 4 batch h-vectors. Partials: [buf][src=rank][batch][gate][unit32].
// smem (floats): Rt G*RPAD=27648 | Hs 128 | Ps 2*3072 | mbar
// ---------------------------------------------------------------------------
#define RT_FLOATS   (G * RPAD)                /* 27648 */
#define HS_OFF      RT_FLOATS
#define PS_OFF      (HS_OFF + NB * KS)        /* 27776 */
#define PBUF_FLOATS (CLU * NB * 3 * KS)       /* 3072  */
#define MB_OFF      (PS_OFF + 2 * PBUF_FLOATS)/* 33920 */
#define SMEM_BYTES  (MB_OFF * 4 + 16)         /* 135696 */
#define RX_BYTES    (PBUF_FLOATS * 4)         /* 12288 per step */

__global__ void __launch_bounds__(TPB, 1) __cluster_dims__(CLU, 1, 1)
scan_kernel(const float* __restrict__ R, float* __restrict__ out)
{
    extern __shared__ float smem[];
    float* Rt = smem;
    float* Hs = smem + HS_OFF;
    float* Ps = smem + PS_OFF;

    const int      tid  = threadIdx.x;
    const uint32_t rank = ctarank();          // 0..7
    const int      cl   = blockIdx.x / CLU;   // cluster 0..15
    const int      b0g  = cl * NB;            // first batch of cluster

    const uint32_t mb_local = smem_u32(smem + MB_OFF);
    if (tid == 0) {
        mbar_init(mb_local,     1);
        mbar_init(mb_local + 8, 1);
    }

    // load own 32-row slice of R, transposed: Rt[g*RPAD + k]
    {
        const float* src = R + (size_t)rank * KS * G;
        for (int i = tid; i < KS * G; i += TPB) {
            const int k = i / G;
            const int g = i - k * G;
            Rt[g * RPAD + k] = src[i];
        }
    }
    if (tid < NB * KS) Hs[tid] = 0.0f;
    __syncthreads();
    cluster_sync();   // barriers + Rt visible cluster-wide before any st.async

    // gemv-thread constants: thread j owns gate columns j, H+j, 2H+j
    const int j       = tid;
    const int dstRank = j >> 5;               // owner CTA of unit j (KS=32)
    const int u32     = j & 31;
    const uint32_t ps_local  = smem_u32(Ps);
    // slot (buf0, src=rank, batch0, gate0, unit u32)
    const uint32_t slot_off  = (uint32_t)(rank * (NB * 3 * KS) + u32) * 4u;
    const uint32_t rem_base0 = mapa_cluster(ps_local + slot_off, (uint32_t)dstRank);
    const uint32_t rem_mb    = mapa_cluster(mb_local, (uint32_t)dstRank);
    const uint32_t BUF_B  = (uint32_t)PBUF_FLOATS * 4u;  // 12288
    const uint32_t BAT_B  = (uint32_t)(3 * KS) * 4u;     // 384
    const uint32_t GATE_B = (uint32_t)KS * 4u;           // 128

    const uint32_t wz_a = smem_u32(Rt) + (uint32_t)j * (RPAD * 4u);
    const uint32_t wr_a = wz_a + (uint32_t)H * (RPAD * 4u);
    const uint32_t wh_a = wr_a + (uint32_t)H * (RPAD * 4u);
    const uint32_t hs_a = smem_u32(Hs);

    // gate-thread constants (tid < 128 = NB*KS)
    const int gb  = tid >> 5;                 // batch-in-cluster 0..3
    const int gu  = tid & 31;                 // unit-in-slice
    const int guu = (int)rank * KS + gu;      // global hidden unit
    const float* xp_gate  = g_xproj + ((size_t)(b0g + gb) * T) * G + guu;
    float*       out_gate = out     + ((size_t)(b0g + gb) * T) * H + guu;

    for (int t = 0; t < T; t++) {
        const int      bi  = t & 1;
        const uint32_t par = (uint32_t)((t >> 1) & 1);

        if (tid == 0) mbar_expect_tx(mb_local + bi * 8, RX_BYTES);

        // prefetch xproj gate inputs (hide GMEM latency under gemv)
        float xz = 0.f, xr = 0.f, xh = 0.f;
        if (tid < NB * KS) {
            const float* xp = xp_gate + (size_t)t * G;
            xz = __ldg(xp); xr = __ldg(xp + H); xh = __ldg(xp + 2 * H);
        }

        // partial GEMV: 3 gates x 4 batches, k in [0,32), packed FFMA2
        ull az[NB], ar[NB], ah[NB];
#pragma unroll
        for (int b = 0; b < NB; b++) { az[b] = 0ULL; ar[b] = 0ULL; ah[b] = 0ULL; }
#pragma unroll
        for (int k4 = 0; k4 < KS / 4; k4++) {
            const uint32_t o = (uint32_t)k4 * 16u;
            ull wa0, wa1, wb0, wb1, wc0, wc1;
            lds_v2b64(wa0, wa1, wz_a + o);
            lds_v2b64(wb0, wb1, wr_a + o);
            lds_v2b64(wc0, wc1, wh_a + o);
#pragma unroll
            for (int b = 0; b < NB; b++) {
                ull p0, p1;
                lds_v2b64(p0, p1, hs_a + (uint32_t)b * (KS * 4u) + o);  // broadcast
                az[b] = ffma2(p0, wa0, az[b]);  az[b] = ffma2(p1, wa1, az[b]);
                ar[b] = ffma2(p0, wb0, ar[b]);  ar[b] = ffma2(p1, wb1, ar[b]);
                ah[b] = ffma2(p0, wc0, ah[b]);  ah[b] = ffma2(p1, wc1, ah[b]);
            }
        }

        // scatter partials to owner CTA (12 stores; counts tx on owner's barrier)
        {
            const uint32_t base = rem_base0 + (uint32_t)bi * BUF_B;
            const uint32_t mbr  = rem_mb + (uint32_t)bi * 8u;
#pragma unroll
            for (int b = 0; b < NB; b++) {
                const uint32_t bb = base + (uint32_t)b * BAT_B;
                st_async_f32(bb,              red2(az[b]), mbr);
                st_async_f32(bb + GATE_B,     red2(ar[b]), mbr);
                st_async_f32(bb + 2u*GATE_B,  red2(ah[b]), mbr);
            }
        }

        // gates: wait for all 8 sources, update own 32 units x 4 batches
        if (tid < NB * KS) {
            mbar_wait(mb_local + bi * 8, par);
            const float* pb = Ps + bi * PBUF_FLOATS;
            float sz = 0.f, sr = 0.f, sh = 0.f;
#pragma unroll
            for (int s = 0; s < CLU; s++) {
                const float* qq = pb + (s * NB + gb) * (3 * KS) + gu;
                sz += qq[0]; sr += qq[KS]; sh += qq[2 * KS];
            }
            const float z  = sigmoid_f(xz + sz);
            const float r  = sigmoid_f(xr + sr);
            const float hh = tanh_f(xh + r * sh);
            const float hn = z * Hs[tid] + (1.0f - z) * hh;
            Hs[tid] = hn;
            out_gate[(size_t)t * H] = hn;
        }
        __syncthreads();   // Hs update visible before next gemv
    }

    cluster_sync();   // keep CTAs alive until all peer traffic drained
}

// ---------------------------------------------------------------------------
// Kernel C: state = tanh(h_last @ dense_w + dense_b)
// ---------------------------------------------------------------------------
__global__ void __launch_bounds__(D) dense_kernel(
    const float* __restrict__ out, const float* __restrict__ w,
    const float* __restrict__ bias, float* __restrict__ state)
{
    const int b = blockIdx.x;
    const int d = threadIdx.x;
    const float* hl = out + ((size_t)b * T + (T - 1)) * H;
    float acc = bias[d];
#pragma unroll 4
    for (int k = 0; k < H; k++)
        acc += hl[k] * w[k * D + d];
    state[(size_t)b * D + d] = tanhf(acc);
}

// ---------------------------------------------------------------------------
extern "C" void kernel_launch(void* const* d_in, const int* in_sizes, int n_in,
                              void* d_out, int out_size)
{
    const float* x     = (const float*)d_in[0];
    const float* kern  = (const float*)d_in[1];
    const float* rkern = (const float*)d_in[2];
    const float* bias  = (const float*)d_in[3];
    const float* dw    = (const float*)d_in[4];
    const float* db    = (const float*)d_in[5];

    float* out   = (float*)d_out;
    float* state = out + (size_t)B * T * H;

    cudaFuncSetAttribute(scan_kernel,
                         cudaFuncAttributeMaxDynamicSharedMemorySize, SMEM_BYTES);

    xproj_kernel<<<(B * T) / XP_ROWS, XP_TPB>>>(x, kern, bias);
    scan_kernel<<<(B / NB) * CLU, TPB, SMEM_BYTES>>>(rkern, out);
    dense_kernel<<<B, D>>>(out, dw, db, state);
}